// round 2
// baseline (speedup 1.0000x reference)
#include <cuda_runtime.h>
#include <cuda_bf16.h>
#include <cstdint>

// Problem shape (fixed by the dataset reference):
//   y_true [B,T,K] f32 (exact one-hot), y_pred [B,T,K] f32, trans [K,K] f32
//   out [B] f32 = logsumexp(forward) - (point_score + trans_score)
static constexpr int B  = 64;
static constexpr int T  = 4096;
static constexpr int K  = 48;
static constexpr int CT = 256;      // timesteps per target-kernel chunk
static constexpr int CH = T / CT;   // 16 chunks

// Per-(batch, chunk) partial target scores. Every slot is written every
// launch, so no zeroing kernel is needed (graph-replay safe).
__device__ float g_part[B * CH];

// ---------------------------------------------------------------------------
// Kernel 1: target = point_score + trans_score, per (b, chunk).
// y_true is one-hot, so per timestep we extract label + pred-at-label + mask,
// then point = m_t * pred[label_t], trans = m_t*m_{t+1}*trans[l_t][l_{t+1}].
// Fully coalesced: e = t*K + i matches memory order exactly.
// ---------------------------------------------------------------------------
__global__ void __launch_bounds__(CT) crf_target_kernel(
    const float* __restrict__ yt, const float* __restrict__ yp,
    const float* __restrict__ tr)
{
    const int b   = blockIdx.y;
    const int ch  = blockIdx.x;
    const int tid = threadIdx.x;

    __shared__ int   lab[CT + 1];
    __shared__ float pl [CT + 1];
    __shared__ int   mk [CT + 1];

    for (int i = tid; i <= CT; i += CT) { mk[i] = 1; lab[i] = 0; pl[i] = 0.0f; }
    __syncthreads();

    const int    t0   = ch * CT;
    const size_t base = ((size_t)b * T + t0) * K;
    // Non-last chunks also process the next chunk's first timestep (for the
    // t -> t+1 transition at the boundary). Last chunk must not read past T.
    const int lim = (t0 + CT >= T) ? (CT * K) : ((CT + 1) * K);

    for (int e = tid; e < lim; e += CT) {
        const float ypv = yp[base + e];
        const float ytv = yt[base + e];
        const int   t   = e / K;
        if (ypv <= -1000000.0f) mk[t] = 0;            // idempotent write: race-safe
        if (ytv > 0.5f) { lab[t] = e - t * K; pl[t] = ypv; }
    }
    __syncthreads();

    float contrib = 0.0f;
    {
        const int t  = tid;          // CT == blockDim.x
        const int gt = t0 + t;
        if (mk[t]) contrib = pl[t];
        if (gt + 1 < T && mk[t] && mk[t + 1])
            contrib += tr[lab[t] * K + lab[t + 1]];
    }

    // Block reduction (deterministic: fixed tree, no atomics).
    #pragma unroll
    for (int o = 16; o > 0; o >>= 1)
        contrib += __shfl_down_sync(0xffffffffu, contrib, o);

    __shared__ float ws[CT / 32];
    if ((tid & 31) == 0) ws[tid >> 5] = contrib;
    __syncthreads();
    if (tid == 0) {
        float s = 0.0f;
        #pragma unroll
        for (int i = 0; i < CT / 32; i++) s += ws[i];
        g_part[b * CH + ch] = s;
    }
}

// ---------------------------------------------------------------------------
// Kernel 2: forward log-partition scan. One block per batch element,
// 64 threads (2 warps), thread j owns state j (j < 48).
//
// Recurrence rewritten with E = exp(trans) held in per-thread registers:
//   c      = s_{t-2}[0]                       (lag-2 normalizer, smem dbl-buf)
//   e_i    = exp(s_i - c)                     (smem, dbl-buffered)
//   new_j  = c + log(sum_i e_i * E[i][j]) + x_j
//   s_j    = m_t ? new_j : s_j
// One __syncthreads per step. x prefetched 4 steps ahead in registers.
// Masks (all_i x_i > -1e6) ballot-computed one step ahead, 4-slot smem ring.
// ---------------------------------------------------------------------------

#define CRF_STEP(TT, PAR, QCUR, QNXT, SL, SL1) {                              \
    const float c  = cbuf[PAR];                                               \
    const int   mm = wall[0][SL] & wall[1][SL];                               \
    const float e  = __expf(s - c);                                           \
    if (act)       ebuf[PAR][j] = e;                                          \
    if (tid == 0)  cbuf[(PAR) ^ 1] = s;                                       \
    const int wa = __all_sync(0xffffffffu, (QNXT) > -1000000.0f);             \
    if (lane == 0) wall[wid][SL1] = wa;                                       \
    __syncthreads();                                                          \
    float d0=0.f,d1=0.f,d2=0.f,d3=0.f,d4=0.f,d5=0.f,d6=0.f,d7=0.f;            \
    _Pragma("unroll")                                                         \
    for (int i = 0; i < K; i += 8) {                                          \
        const float4 u = *(const float4*)(&ebuf[PAR][i]);                     \
        const float4 v = *(const float4*)(&ebuf[PAR][i + 4]);                 \
        d0 = fmaf(u.x, E[i + 0], d0); d1 = fmaf(u.y, E[i + 1], d1);           \
        d2 = fmaf(u.z, E[i + 2], d2); d3 = fmaf(u.w, E[i + 3], d3);           \
        d4 = fmaf(v.x, E[i + 4], d4); d5 = fmaf(v.y, E[i + 5], d5);           \
        d6 = fmaf(v.z, E[i + 6], d6); d7 = fmaf(v.w, E[i + 7], d7);           \
    }                                                                         \
    const float dot  = ((d0 + d1) + (d2 + d3)) + ((d4 + d5) + (d6 + d7));     \
    const float news = c + __logf(dot) + (QCUR);                              \
    s = mm ? news : s;                                                        \
    { const int tn = (TT) + 4;                                                \
      QCUR = (act && tn < T) ? __ldg(xp + (size_t)tn * K) : 1e30f; }          \
}

__global__ void __launch_bounds__(64, 1) crf_forward_kernel(
    const float* __restrict__ yp, const float* __restrict__ tr,
    float* __restrict__ out)
{
    const int  b    = blockIdx.x;
    const int  tid  = threadIdx.x;
    const int  j    = tid;
    const bool act  = (j < K);
    const int  wid  = tid >> 5;
    const int  lane = tid & 31;

    __shared__ __align__(16) float ebuf[2][K];
    __shared__ float cbuf[2];
    __shared__ int   wall[2][4];
    __shared__ float red[64];

    // E[i] = exp(trans[i][j]) — thread j's column, in registers.
    float E[K];
    if (act) {
        const float* tcol = tr + j;
        #pragma unroll
        for (int i = 0; i < K; i++) E[i] = __expf(tcol[i * K]);
    } else {
        #pragma unroll
        for (int i = 0; i < K; i++) E[i] = 0.0f;
    }

    const float* xp = yp + (size_t)b * T * K + (act ? j : 0);

    // Prefetch: x0 (init) and steps 1..4 into the register queue.
    const float x0 = act ? __ldg(xp)             : 1e30f;
    float q0 = act ? __ldg(xp + (size_t)1 * K) : 1e30f;   // step 1
    float q1 = act ? __ldg(xp + (size_t)2 * K) : 1e30f;   // step 2
    float q2 = act ? __ldg(xp + (size_t)3 * K) : 1e30f;   // step 3
    float q3 = act ? __ldg(xp + (size_t)4 * K) : 1e30f;   // step 4

    // Masks for steps 0 and 1; publish.
    {
        const int wa0 = __all_sync(0xffffffffu, x0 > -1000000.0f);
        const int wa1 = __all_sync(0xffffffffu, q0 > -1000000.0f);
        if (lane == 0) { wall[wid][0] = wa0; wall[wid][1] = wa1; }
    }
    __syncthreads();

    const int m0 = wall[0][0] & wall[1][0];
    float s = m0 ? x0 : 0.0f;                 // init = mask_0 * y_pred[:,0]
    if (tid == 0) cbuf[1] = s;                // normalizer for iters 1 & 2
    __syncthreads();

    // Main scan: t = 1 .. T-1 (4095 steps). tb ≡ 1 (mod 4) so all queue
    // slots / parities / mask slots are compile-time constants per instance.
    int tb = 1;
    for (; tb + 3 < T; tb += 4) {
        CRF_STEP(tb + 0, 1, q0, q1, 1, 2)
        CRF_STEP(tb + 1, 0, q1, q2, 2, 3)
        CRF_STEP(tb + 2, 1, q2, q3, 3, 0)
        CRF_STEP(tb + 3, 0, q3, q0, 0, 1)
    }
    // Tail: T-1 = 4095 -> 3 remaining steps (4093, 4094, 4095).
    CRF_STEP(tb + 0, 1, q0, q1, 1, 2)
    CRF_STEP(tb + 1, 0, q1, q2, 2, 3)
    CRF_STEP(tb + 2, 1, q2, q3, 3, 0)

    // Final logsumexp over 48 states + subtract target.
    red[tid] = act ? s : -3.0e38f;
    __syncthreads();
    if (wid == 0) {
        const float a  = red[lane];
        const float bb = red[lane + 32];
        float mx = fmaxf(a, bb);
        #pragma unroll
        for (int o = 16; o > 0; o >>= 1)
            mx = fmaxf(mx, __shfl_xor_sync(0xffffffffu, mx, o));
        float sm = __expf(a - mx) + __expf(bb - mx);
        #pragma unroll
        for (int o = 16; o > 0; o >>= 1)
            sm += __shfl_xor_sync(0xffffffffu, sm, o);
        if (lane == 0) {
            float tgt = 0.0f;
            #pragma unroll
            for (int i = 0; i < CH; i++) tgt += g_part[b * CH + i];
            out[b] = mx + __logf(sm) - tgt;
        }
    }
}

// ---------------------------------------------------------------------------
extern "C" void kernel_launch(void* const* d_in, const int* in_sizes, int n_in,
                              void* d_out, int out_size)
{
    const float* y_true = (const float*)d_in[0];
    const float* y_pred = (const float*)d_in[1];
    const float* trans  = (const float*)d_in[2];
    float* out = (float*)d_out;

    dim3 grid_t(CH, B);
    crf_target_kernel<<<grid_t, CT>>>(y_true, y_pred, trans);
    crf_forward_kernel<<<B, 64>>>(y_pred, trans, out);
}

// round 5
// speedup vs baseline: 1.9238x; 1.9238x over previous
#include <cuda_runtime.h>
#include <cuda_bf16.h>
#include <cstdint>

// Shapes fixed by the dataset reference:
//   y_true [B,T,K] f32 (exact one-hot), y_pred [B,T,K] f32, trans [K,K] f32
//   out [B] f32 = logsumexp(forward) - (point_score + trans_score)
static constexpr int B  = 64;
static constexpr int T  = 4096;
static constexpr int K  = 48;
static constexpr int CT = 256;      // timesteps per target-kernel chunk
static constexpr int CH = T / CT;   // 16 chunks

// Per-(batch, chunk) partial target scores. Every slot written every launch.
__device__ float g_part[B * CH];

// ---------------------------------------------------------------------------
// Kernel 1: target = point_score + trans_score, per (b, chunk).
// y_true is exact one-hot: extract label, pred-at-label, mask per timestep.
// ---------------------------------------------------------------------------
__global__ void __launch_bounds__(CT) crf_target_kernel(
    const float* __restrict__ yt, const float* __restrict__ yp,
    const float* __restrict__ tr)
{
    const int b   = blockIdx.y;
    const int ch  = blockIdx.x;
    const int tid = threadIdx.x;

    __shared__ int   lab[CT + 1];
    __shared__ float pl [CT + 1];
    __shared__ int   mk [CT + 1];

    for (int i = tid; i <= CT; i += CT) { mk[i] = 1; lab[i] = 0; pl[i] = 0.0f; }
    __syncthreads();

    const int    t0   = ch * CT;
    const size_t base = ((size_t)b * T + t0) * K;
    const int lim = (t0 + CT >= T) ? (CT * K) : ((CT + 1) * K);

    for (int e = tid; e < lim; e += CT) {
        const float ypv = yp[base + e];
        const float ytv = yt[base + e];
        const int   t   = e / K;
        if (ypv <= -1000000.0f) mk[t] = 0;            // idempotent: race-safe
        if (ytv > 0.5f) { lab[t] = e - t * K; pl[t] = ypv; }
    }
    __syncthreads();

    float contrib = 0.0f;
    {
        const int t  = tid;
        const int gt = t0 + t;
        if (mk[t]) contrib = pl[t];
        if (gt + 1 < T && mk[t] && mk[t + 1])
            contrib += tr[lab[t] * K + lab[t + 1]];
    }

    #pragma unroll
    for (int o = 16; o > 0; o >>= 1)
        contrib += __shfl_down_sync(0xffffffffu, contrib, o);

    __shared__ float ws[CT / 32];
    if ((tid & 31) == 0) ws[tid >> 5] = contrib;
    __syncthreads();
    if (tid == 0) {
        float s = 0.0f;
        #pragma unroll
        for (int i = 0; i < CT / 32; i++) s += ws[i];
        g_part[b * CH + ch] = s;
    }
}

// ---------------------------------------------------------------------------
// f32x2 packed helpers (sm_103a)
// ---------------------------------------------------------------------------
__device__ __forceinline__ unsigned long long pk2(float lo, float hi) {
    unsigned long long r;
    asm("mov.b64 %0, {%1, %2};" : "=l"(r) : "f"(lo), "f"(hi));
    return r;
}
__device__ __forceinline__ void upk2(unsigned long long v, float& lo, float& hi) {
    asm("mov.b64 {%0, %1}, %2;" : "=f"(lo), "=f"(hi) : "l"(v));
}
__device__ __forceinline__ unsigned long long fma2_(unsigned long long a,
                                                    unsigned long long b,
                                                    unsigned long long c) {
    unsigned long long d;
    asm("fma.rn.f32x2 %0, %1, %2, %3;" : "=l"(d) : "l"(a), "l"(b), "l"(c));
    return d;
}
__device__ __forceinline__ unsigned long long add2_(unsigned long long a,
                                                    unsigned long long b) {
    unsigned long long d;
    asm("add.rn.f32x2 %0, %1, %2;" : "=l"(d) : "l"(a), "l"(b));
    return d;
}
__device__ __forceinline__ unsigned long long mul2_(unsigned long long a,
                                                    unsigned long long b) {
    unsigned long long d;
    asm("mul.rn.f32x2 %0, %1, %2;" : "=l"(d) : "l"(a), "l"(b));
    return d;
}

// ---------------------------------------------------------------------------
// Kernel 2: forward scan, prob-domain with lagged rescale. One WARP per batch.
// Thread l owns states (2l, 2l+1) for l < 24; lanes 24..31 idle-but-voting.
//
//   W_j(t) = exp(s_j(t) - C(t)),  C(t) = C(t-1) + ln W_0(t-1)
//   W_j(t) = (sum_i W_i(t-1) E_ij) * exp(x_j(t)) * rcp(W_0(t-1))
// exp(x), rcp, log all OFF the critical path. One __syncwarp per step.
// W published pre-duplicated: wbuf[p][l] = (w_e,w_e,w_o,w_o) -> one STS.128;
// the dot is 24 broadcast LDS.128 + 48 packed fma.rn.f32x2 per thread.
// ---------------------------------------------------------------------------

#define CRF_STEP(TT, P, QC) {                                                 \
    if (act) wbuf[P][l] = make_ulonglong2(pk2(wlo, wlo), pk2(whi, whi));      \
    const int um = __all_sync(0xffffffffu,                                    \
                              (QC).x > -1000000.0f && (QC).y > -1000000.0f);  \
    const float f0 = __expf((QC).x);                                          \
    const float f1 = __expf((QC).y);                                          \
    { const int tn = (TT) + 4;                                                \
      QC = (act && tn < T) ? __ldg(xp2 + (size_t)tn * (K / 2))                \
                           : make_float2(1e30f, 1e30f); }                     \
    __syncwarp();                                                             \
    const float w0 = ((const float*)&wbuf[P][0])[0];                          \
    float rr; asm("rcp.approx.f32 %0, %1;" : "=f"(rr) : "f"(w0));             \
    const float lw = __logf(w0);                                              \
    const unsigned long long FR = pk2(f0 * rr, f1 * rr);                      \
    unsigned long long d0 = 0ull, d1 = 0ull, d2 = 0ull, d3 = 0ull;            \
    _Pragma("unroll")                                                         \
    for (int i = 0; i < 24; i += 2) {                                         \
        const ulonglong2 aa = wbuf[P][i];                                     \
        const ulonglong2 bb = wbuf[P][i + 1];                                 \
        d0 = fma2_(aa.x, E2[2 * i],     d0);                                  \
        d1 = fma2_(aa.y, E2[2 * i + 1], d1);                                  \
        d2 = fma2_(bb.x, E2[2 * i + 2], d2);                                  \
        d3 = fma2_(bb.y, E2[2 * i + 3], d3);                                  \
    }                                                                         \
    const unsigned long long dd = add2_(add2_(d0, d1), add2_(d2, d3));        \
    float nlo, nhi; upk2(mul2_(dd, FR), nlo, nhi);                            \
    if (um) { wlo = nlo; whi = nhi; C += lw; }                                \
}

__global__ void __launch_bounds__(32, 1) crf_forward_kernel(
    const float* __restrict__ yp, const float* __restrict__ tr,
    float* __restrict__ out)
{
    const int  b    = blockIdx.x;
    const int  l    = threadIdx.x;
    const bool act  = (l < K / 2);          // 24 active lanes

    __shared__ ulonglong2 wbuf[2][K / 2];   // dup-pairs, double-buffered

    // E2[i] = (exp(trans[i][2l]), exp(trans[i][2l+1])) packed, in registers.
    unsigned long long E2[K];
    {
        const int j0 = act ? 2 * l : 0;
        #pragma unroll
        for (int i = 0; i < K; i++) {
            const float e0 = act ? __expf(tr[i * K + j0])     : 0.0f;
            const float e1 = act ? __expf(tr[i * K + j0 + 1]) : 0.0f;
            E2[i] = pk2(e0, e1);
        }
    }

    const float2* xp2 = (const float2*)yp + (size_t)b * T * (K / 2) + (act ? l : 0);

    // t = 0 init + prefetch t = 1..4.
    const float2 x0 = act ? __ldg(xp2) : make_float2(1e30f, 1e30f);
    float2 q0 = act ? __ldg(xp2 + 1 * (K / 2)) : make_float2(1e30f, 1e30f);
    float2 q1 = act ? __ldg(xp2 + 2 * (K / 2)) : make_float2(1e30f, 1e30f);
    float2 q2 = act ? __ldg(xp2 + 3 * (K / 2)) : make_float2(1e30f, 1e30f);
    float2 q3 = act ? __ldg(xp2 + 4 * (K / 2)) : make_float2(1e30f, 1e30f);

    const int m0 = __all_sync(0xffffffffu,
                              x0.x > -1000000.0f && x0.y > -1000000.0f);
    float wlo = __expf(m0 ? x0.x : 0.0f);   // W(0) = exp(s(0)), C(0) = 0
    float whi = __expf(m0 ? x0.y : 0.0f);
    float C   = 0.0f;

    // Steps t = 1..4095; buffer parity = t & 1; unroll 4 (parities 1,0,1,0).
    int tb = 1;
    for (; tb + 3 < T; tb += 4) {
        CRF_STEP(tb + 0, 1, q0)
        CRF_STEP(tb + 1, 0, q1)
        CRF_STEP(tb + 2, 1, q2)
        CRF_STEP(tb + 3, 0, q3)
    }
    // Tail: t = 4093, 4094, 4095.
    CRF_STEP(tb + 0, 1, q0)
    CRF_STEP(tb + 1, 0, q1)
    CRF_STEP(tb + 2, 1, q2)

    // log_norm = C + log(sum_j W_j); subtract target.
    float sum = act ? (wlo + whi) : 0.0f;
    #pragma unroll
    for (int o = 16; o > 0; o >>= 1)
        sum += __shfl_xor_sync(0xffffffffu, sum, o);

    if (l == 0) {
        float tgt = 0.0f;
        #pragma unroll
        for (int i = 0; i < CH; i++) tgt += g_part[b * CH + i];
        out[b] = C + __logf(sum) - tgt;
    }
}

// ---------------------------------------------------------------------------
extern "C" void kernel_launch(void* const* d_in, const int* in_sizes, int n_in,
                              void* d_out, int out_size)
{
    const float* y_true = (const float*)d_in[0];
    const float* y_pred = (const float*)d_in[1];
    const float* trans  = (const float*)d_in[2];
    float* out = (float*)d_out;

    dim3 grid_t(CH, B);
    crf_target_kernel<<<grid_t, CT>>>(y_true, y_pred, trans);
    crf_forward_kernel<<<B, 32>>>(y_pred, trans, out);
}

// round 6
// speedup vs baseline: 2.4605x; 1.2790x over previous
#include <cuda_runtime.h>
#include <cuda_bf16.h>
#include <cstdint>

// Shapes fixed by the dataset reference:
//   y_true [B,T,K] f32 (exact one-hot), y_pred [B,T,K] f32, trans [K,K] f32
//   out [B] f32 = logsumexp(forward) - (point_score + trans_score)
static constexpr int B  = 64;
static constexpr int T  = 4096;
static constexpr int K  = 48;
static constexpr int CT = 256;      // timesteps per target-kernel chunk
static constexpr int CH = T / CT;   // 16 chunks

// Per-(batch, chunk) partial target scores. Every slot written every launch.
__device__ float g_part[B * CH];

// ---------------------------------------------------------------------------
// Kernel 1: target = point_score + trans_score, per (b, chunk).
// ---------------------------------------------------------------------------
__global__ void __launch_bounds__(CT) crf_target_kernel(
    const float* __restrict__ yt, const float* __restrict__ yp,
    const float* __restrict__ tr)
{
    const int b   = blockIdx.y;
    const int ch  = blockIdx.x;
    const int tid = threadIdx.x;

    __shared__ int   lab[CT + 1];
    __shared__ float pl [CT + 1];
    __shared__ int   mk [CT + 1];

    for (int i = tid; i <= CT; i += CT) { mk[i] = 1; lab[i] = 0; pl[i] = 0.0f; }
    __syncthreads();

    const int    t0   = ch * CT;
    const size_t base = ((size_t)b * T + t0) * K;
    const int lim = (t0 + CT >= T) ? (CT * K) : ((CT + 1) * K);

    for (int e = tid; e < lim; e += CT) {
        const float ypv = yp[base + e];
        const float ytv = yt[base + e];
        const int   t   = e / K;
        if (ypv <= -1000000.0f) mk[t] = 0;            // idempotent: race-safe
        if (ytv > 0.5f) { lab[t] = e - t * K; pl[t] = ypv; }
    }
    __syncthreads();

    float contrib = 0.0f;
    {
        const int t  = tid;
        const int gt = t0 + t;
        if (mk[t]) contrib = pl[t];
        if (gt + 1 < T && mk[t] && mk[t + 1])
            contrib += tr[lab[t] * K + lab[t + 1]];
    }

    #pragma unroll
    for (int o = 16; o > 0; o >>= 1)
        contrib += __shfl_down_sync(0xffffffffu, contrib, o);

    __shared__ float ws[CT / 32];
    if ((tid & 31) == 0) ws[tid >> 5] = contrib;
    __syncthreads();
    if (tid == 0) {
        float s = 0.0f;
        #pragma unroll
        for (int i = 0; i < CT / 32; i++) s += ws[i];
        g_part[b * CH + ch] = s;
    }
}

// ---------------------------------------------------------------------------
// f32x2 packed helpers (sm_103a)
// ---------------------------------------------------------------------------
__device__ __forceinline__ unsigned long long pk2(float lo, float hi) {
    unsigned long long r;
    asm("mov.b64 %0, {%1, %2};" : "=l"(r) : "f"(lo), "f"(hi));
    return r;
}
__device__ __forceinline__ void upk2(unsigned long long v, float& lo, float& hi) {
    asm("mov.b64 {%0, %1}, %2;" : "=f"(lo), "=f"(hi) : "l"(v));
}
__device__ __forceinline__ unsigned long long fma2_(unsigned long long a,
                                                    unsigned long long b,
                                                    unsigned long long c) {
    unsigned long long d;
    asm("fma.rn.f32x2 %0, %1, %2, %3;" : "=l"(d) : "l"(a), "l"(b), "l"(c));
    return d;
}
__device__ __forceinline__ unsigned long long add2_(unsigned long long a,
                                                    unsigned long long b) {
    unsigned long long d;
    asm("add.rn.f32x2 %0, %1, %2;" : "=l"(d) : "l"(a), "l"(b));
    return d;
}

// ---------------------------------------------------------------------------
// Kernel 2: forward scan, prob-domain, lagged rescale. 2 warps per batch,
// ONE state per lane (48 active lanes of 64).
//
//   W_j(t) = (sum_i W_i(t-1) E_ij) * exp(x_j(t)) * rcp(W_0(t-1))
//   C(t)   = C(t-1) + ln W_0(t-1)
//
// State published as plain float[48] (parity double-buffered); each lane
// reads it back as 12 broadcast LDS.128 and does 24 packed fma.rn.f32x2
// (packed along the reduction dim), then one horizontal add.
// Masks are voted ONE STEP AHEAD on data prefetched 8 steps ahead (never
// scoreboard-stalls) and exchanged cross-warp via parity-buffered smem
// flags ordered by the per-step bar.sync.
// ---------------------------------------------------------------------------

#define CRF_STEP(TT, P, QA, QAN, QB) {                                        \
    __syncthreads();                                                          \
    const int mm = vflag[0][P] & vflag[1][P];                                 \
    const float f = __expf(QA);                                               \
    const int vn = __all_sync(0xffffffffu, (QAN) > -1000000.0f);              \
    if (l == 0) vflag[wd][(P) ^ 1] = vn;                                      \
    ulonglong2 wv[12];                                                        \
    _Pragma("unroll")                                                         \
    for (int c = 0; c < 12; c++) wv[c] = wb2[P][c];                           \
    float w0, wdum; upk2(wv[0].x, w0, wdum);                                  \
    float rr; asm("rcp.approx.f32 %0, %1;" : "=f"(rr) : "f"(w0));             \
    const float lw = __logf(w0);                                              \
    unsigned long long d0 = 0ull, d1 = 0ull, d2 = 0ull, d3 = 0ull;            \
    _Pragma("unroll")                                                         \
    for (int c = 0; c < 12; c += 2) {                                         \
        d0 = fma2_(wv[c].x,     E2[2 * c],     d0);                           \
        d1 = fma2_(wv[c].y,     E2[2 * c + 1], d1);                           \
        d2 = fma2_(wv[c + 1].x, E2[2 * c + 2], d2);                           \
        d3 = fma2_(wv[c + 1].y, E2[2 * c + 3], d3);                           \
    }                                                                         \
    const unsigned long long dd = add2_(add2_(d0, d1), add2_(d2, d3));        \
    float dx, dy; upk2(dd, dx, dy);                                           \
    const float wn = (dx + dy) * (f * rr);                                    \
    if (mm) { wj = wn; C += lw; }                                             \
    if (act) wbufF[(P) ^ 1][j] = wj;                                          \
    QA = QB;                                                                  \
    { const int tn = (TT) + 8;                                                \
      QB = (tn < T) ? __ldg(xp + (size_t)tn * K) : 1e30f; }                   \
}

__global__ void __launch_bounds__(64, 1) crf_forward_kernel(
    const float* __restrict__ yp, const float* __restrict__ tr,
    float* __restrict__ out)
{
    const int  b   = blockIdx.x;
    const int  tid = threadIdx.x;
    const int  wd  = tid >> 5;              // warp id (0/1)
    const int  l   = tid & 31;              // lane
    const bool act = (l < 24);
    const int  j   = 24 * wd + (act ? l : 23);   // state owned by this lane

    __shared__ __align__(16) float wbufF[2][K];  // state, parity-buffered
    __shared__ int   vflag[2][2];                // [warp][parity] mask votes
    __shared__ float redw[K];
    const ulonglong2 (*wb2)[12] = (const ulonglong2 (*)[12])wbufF;

    // E2[p] = (exp(trans[2p][j]), exp(trans[2p+1][j])) packed, registers.
    unsigned long long E2[K / 2];
    #pragma unroll
    for (int p = 0; p < K / 2; p++)
        E2[p] = pk2(__expf(tr[(2 * p) * K + j]),
                    __expf(tr[(2 * p + 1) * K + j]));

    const float* xp = yp + (size_t)b * T * K + j;

    // Prime: x0 (t=0), qA = t 1..4, qB = t 5..8.
    const float x0 = __ldg(xp);
    float qA0 = __ldg(xp + (size_t)1 * K), qA1 = __ldg(xp + (size_t)2 * K);
    float qA2 = __ldg(xp + (size_t)3 * K), qA3 = __ldg(xp + (size_t)4 * K);
    float qB0 = __ldg(xp + (size_t)5 * K), qB1 = __ldg(xp + (size_t)6 * K);
    float qB2 = __ldg(xp + (size_t)7 * K), qB3 = __ldg(xp + (size_t)8 * K);

    // Votes for t=0 (slot 0) and t=1 (slot 1). Extra lanes duplicate state
    // 23's x, which cannot change the AND.
    {
        const int v0 = __all_sync(0xffffffffu, x0  > -1000000.0f);
        const int v1 = __all_sync(0xffffffffu, qA0 > -1000000.0f);
        if (l == 0) { vflag[wd][0] = v0; vflag[wd][1] = v1; }
    }
    __syncthreads();

    const int m0 = vflag[0][0] & vflag[1][0];
    float wj = __expf(m0 ? x0 : 0.0f);      // W(0) = exp(s(0)), C(0) = 0
    float C  = 0.0f;
    if (act) wbufF[1][j] = wj;              // step t=1 reads parity 1

    // Steps t = 1..4095; parity = t & 1; unroll 4 (parities 1,0,1,0).
    // Instance k votes for t+1 using qA[(k+1)%4]; for k=3 that register was
    // rotated at k=0 and holds exactly t+1's value.
    int tb = 1;
    for (; tb + 3 < T; tb += 4) {
        CRF_STEP(tb + 0, 1, qA0, qA1, qB0)
        CRF_STEP(tb + 1, 0, qA1, qA2, qB1)
        CRF_STEP(tb + 2, 1, qA2, qA3, qB2)
        CRF_STEP(tb + 3, 0, qA3, qA0, qB3)
    }
    // Tail: t = 4093, 4094, 4095.
    CRF_STEP(tb + 0, 1, qA0, qA1, qB0)
    CRF_STEP(tb + 1, 0, qA1, qA2, qB1)
    CRF_STEP(tb + 2, 1, qA2, qA3, qB2)

    // log_norm = C + log(sum_j W_j); subtract target. C is warp-uniform.
    if (act) redw[j] = wj;
    __syncthreads();
    if (tid < 16) {
        float v = redw[tid] + redw[tid + 16] + redw[tid + 32];
        #pragma unroll
        for (int o = 8; o > 0; o >>= 1)
            v += __shfl_xor_sync(0x0000ffffu, v, o);
        if (tid == 0) {
            float tgt = 0.0f;
            #pragma unroll
            for (int i = 0; i < CH; i++) tgt += g_part[b * CH + i];
            out[b] = C + __logf(v) - tgt;
        }
    }
}

// ---------------------------------------------------------------------------
extern "C" void kernel_launch(void* const* d_in, const int* in_sizes, int n_in,
                              void* d_out, int out_size)
{
    const float* y_true = (const float*)d_in[0];
    const float* y_pred = (const float*)d_in[1];
    const float* trans  = (const float*)d_in[2];
    float* out = (float*)d_out;

    dim3 grid_t(CH, B);
    crf_target_kernel<<<grid_t, CT>>>(y_true, y_pred, trans);
    crf_forward_kernel<<<B, 64>>>(y_pred, trans, out);
}